// round 13
// baseline (speedup 1.0000x reference)
#include <cuda_runtime.h>
#include <cuda_fp16.h>
#include <cstdint>

// ---------------- problem constants ----------------
static constexpr int B = 512, S = 128, D = 512, A = 128;
static constexpr float EPS = 1e-7f;

// ---------------- device scratch (no allocs allowed) ----------------
__device__ __align__(16) __half g_wt[A * D];      // W^T fp16 [a][k]
__device__ float g_kv[B * S];
__device__ float g_mv;
__device__ __align__(16) float g_P1h[B * 2 * D];  // per-half sum_s x*exp(kv)*mask
__device__ __align__(16) float g_P2h[B * 2 * D];  // per-half sum_s x*mask

// ---------------- tiling: CTA = (batch, half) -> 64 s-rows ----------------
static constexpr int MS     = 64;
static constexpr int KC     = 32;                 // k per chunk
static constexpr int NCHUNK = D / KC;             // 16

// X resident fp16: [64 rows][520 h] = 1040 B/row -> 66560 B
static constexpr int XROWB  = 520 * 2;
static constexpr int XTOT_B = MS * XROWB;         // 66560
// X fp32 staging: [64 rows][40 f32] = 160 B/row -> 10240 B, 2 bufs
static constexpr int SROWB  = 40 * 4;             // 160
static constexpr int SBUF_B = MS * SROWB;         // 10240
// W stage: [128 rows][40 h] = 80 B/row -> 10240 B, 2 bufs
static constexpr int WROWB  = 40 * 2;             // 80
static constexpr int WBUF_B = 128 * WROWB;        // 10240
static constexpr int OFF_X    = 0;
static constexpr int OFF_XS   = XTOT_B;                      // 66560
static constexpr int OFF_W    = OFF_XS + 2 * SBUF_B;         // 87040
static constexpr int OFF_BIAS = OFF_W + 2 * WBUF_B;          // 107520
static constexpr int OFF_U    = OFF_BIAS + 512;
static constexpr int OFF_PART = OFF_U + 512;                 // float[64][4]
static constexpr int OFF_W1   = OFF_PART + 1024;             // exp(kv)*mask [64]
static constexpr int OFF_MASK = OFF_W1 + 256;                // mask [64]
static constexpr int SMEM_TOTAL = OFF_MASK + 256;            // 110336 (2 CTAs/SM)

// ---------------- baseline-ISA helpers (sm_100 plain) ----------------
__device__ __forceinline__ uint32_t smem_u32(const void* p) {
    return (uint32_t)__cvta_generic_to_shared(p);
}

#define CP_ASYNC16(dst, src) \
    asm volatile("cp.async.cg.shared.global [%0], [%1], 16;" :: "r"(dst), "l"(src))
#define CP_COMMIT() asm volatile("cp.async.commit_group;")
#define CP_WAIT_ALL() asm volatile("cp.async.wait_group 0;")

#define LDSM_X4(r, addr) \
    asm volatile("ldmatrix.sync.aligned.m8n8.x4.shared.b16 {%0,%1,%2,%3}, [%4];" \
        : "=r"((r)[0]), "=r"((r)[1]), "=r"((r)[2]), "=r"((r)[3]) : "r"(addr))

#define MMA_F16(d, a, b0, b1) \
    asm volatile("mma.sync.aligned.m16n8k16.row.col.f32.f16.f16.f32 " \
        "{%0,%1,%2,%3}, {%4,%5,%6,%7}, {%8,%9}, {%0,%1,%2,%3};" \
        : "+f"((d)[0]), "+f"((d)[1]), "+f"((d)[2]), "+f"((d)[3]) \
        : "r"((a)[0]), "r"((a)[1]), "r"((a)[2]), "r"((a)[3]), "r"(b0), "r"(b1))

__device__ __forceinline__ uint32_t f2h2(float a, float b) {
    __half2 h = __floats2half2_rn(a, b);
    return *(uint32_t*)&h;
}

__device__ __forceinline__ float fast_tanh(float x) {
    float a = fabsf(x);
    float t = __expf(-2.0f * a);
    float r = (1.0f - t) / (1.0f + t);
    return copysignf(r, x);
}

// ---------------- kernel 0: transpose W to fp16 ----------------
__global__ void prep_w_kernel(const float* __restrict__ W) {
    int idx = blockIdx.x * blockDim.x + threadIdx.x;
    if (idx < D * A) {
        int k = idx / A, a = idx % A;
        g_wt[a * D + k] = __float2half_rn(W[idx]);
    }
}

// ---------------- kernel 1: fused GEMM + tanh + kv + pooling ----------------
// All global traffic via cp.async. Per chunk: staging fp32 feeds both the
// A-fragment LDS+cvt path (R6-proven) and a cvt->STS.128 pass building the
// resident fp16 X used by the pool tail. One barrier per chunk.
__global__ __launch_bounds__(256, 2)
void gemm_kv_pool_kernel(const float* __restrict__ x,
                         const float* __restrict__ mask,
                         const float* __restrict__ bias,
                         const float* __restrict__ u) {
    extern __shared__ char smem[];
    const uint32_t sb = smem_u32(smem);
    const int tid = threadIdx.x;
    const int wid = tid >> 5;
    const int l   = tid & 31;
    const int b    = blockIdx.x >> 1;
    const int half = blockIdx.x & 1;
    const int srow0 = half * MS;

    if (tid < A) {
        *(float*)(smem + OFF_BIAS + tid * 4) = bias[tid];
        *(float*)(smem + OFF_U + tid * 4) = u[tid];
    }
    if (tid < MS)
        *(float*)(smem + OFF_MASK + tid * 4) = mask[b * S + srow0 + tid];

    const int wm = wid >> 2, wn = wid & 3;       // 2 x 4 warp grid, tile 32x32
    const int m0 = wm * 32, n0 = wn * 32;

    const float* xb = x + (size_t)(b * S + srow0) * D;

    // A-fragment lane geometry on fp32 staging (LDS.64 + cvt)
    const int ar = l >> 2;
    const int ac = (l & 3) << 1;
    // B ldmatrix pointer (within a W stage)
    const uint32_t bOff = (uint32_t)((n0 + ((l >> 4) << 3) + (l & 7)) * WROWB
                                     + (((l >> 3) & 1) << 3) * 2);

    // cvt pass geometry: row = tid>>2, col group (tid&3)*8 (8 f32 -> 8 halves)
    const int cr = tid >> 2, cc = (tid & 3) << 3;

    float acc[2][4][4];
    #pragma unroll
    for (int mt = 0; mt < 2; mt++)
        #pragma unroll
        for (int nt = 0; nt < 4; nt++)
            #pragma unroll
            for (int q = 0; q < 4; q++) acc[mt][nt][q] = 0.0f;

    auto issueChunk = [&](int c) {
        const uint32_t xS = sb + OFF_XS + (c & 1) * SBUF_B;
        const uint32_t wS = sb + OFF_W + (c & 1) * WBUF_B;
        #pragma unroll
        for (int t = 0; t < 2; t++) {
            int slot = tid + t * 256;
            int row = slot >> 3, j = slot & 7;
            CP_ASYNC16(xS + row * SROWB + j * 16,
                       (const char*)(xb + (size_t)row * D + c * KC) + j * 16);
        }
        #pragma unroll
        for (int t = 0; t < 2; t++) {
            int slot = tid + t * 256;
            int row = slot >> 2, j = slot & 3;
            CP_ASYNC16(wS + row * WROWB + j * 16,
                       (const char*)(g_wt + (size_t)row * D + c * KC) + j * 16);
        }
        CP_COMMIT();
    };

    issueChunk(0);

    #pragma unroll 1
    for (int c = 0; c < NCHUNK; c++) {
        CP_WAIT_ALL();
        __syncthreads();
        if (c + 1 < NCHUNK) issueChunk(c + 1);

        const uint32_t xS = sb + OFF_XS + (c & 1) * SBUF_B;
        const uint32_t wS = sb + OFF_W + (c & 1) * WBUF_B;

        // ---- cvt pass: staging fp32 -> resident fp16 (single STS.128) ----
        {
            float4 v0 = *(const float4*)(smem + (xS - sb) + cr * SROWB + cc * 4);
            float4 v1 = *(const float4*)(smem + (xS - sb) + cr * SROWB + cc * 4 + 16);
            __half2 h0 = __floats2half2_rn(v0.x, v0.y);
            __half2 h1 = __floats2half2_rn(v0.z, v0.w);
            __half2 h2 = __floats2half2_rn(v1.x, v1.y);
            __half2 h3 = __floats2half2_rn(v1.z, v1.w);
            uint32_t dst = (uint32_t)(cr * XROWB + (c * KC + cc) * 2);  // 16B-aligned
            *(uint4*)(smem + OFF_X + dst) =
                make_uint4(*(uint32_t*)&h0, *(uint32_t*)&h1,
                           *(uint32_t*)&h2, *(uint32_t*)&h3);
        }

        // ---- MMA: 2 k-steps of 16 ----
        #pragma unroll
        for (int ks = 0; ks < 2; ks++) {
            const int kc = ks * 16;
            uint32_t ah[2][4], bb[2][4];
            #pragma unroll
            for (int mt = 0; mt < 2; mt++) {
                const uint32_t boff = (uint32_t)((m0 + mt * 16 + ar) * SROWB
                                                 + (kc + ac) * 4) + (xS - sb);
                float2 v0 = *(const float2*)(smem + boff);
                float2 v1 = *(const float2*)(smem + boff + 8 * SROWB);
                float2 v2 = *(const float2*)(smem + boff + 32);
                float2 v3 = *(const float2*)(smem + boff + 8 * SROWB + 32);
                ah[mt][0] = f2h2(v0.x, v0.y);
                ah[mt][1] = f2h2(v1.x, v1.y);
                ah[mt][2] = f2h2(v2.x, v2.y);
                ah[mt][3] = f2h2(v3.x, v3.y);
            }
            LDSM_X4(bb[0], wS + bOff + kc * 2);
            LDSM_X4(bb[1], wS + bOff + 16 * WROWB + kc * 2);
            #pragma unroll
            for (int mt = 0; mt < 2; mt++)
                #pragma unroll
                for (int nb = 0; nb < 2; nb++) {
                    MMA_F16(acc[mt][2 * nb],     ah[mt], bb[nb][0], bb[nb][1]);
                    MMA_F16(acc[mt][2 * nb + 1], ah[mt], bb[nb][2], bb[nb][3]);
                }
        }
    }
    __syncthreads();   // resident X fully written; staging no longer needed

    // ---- kv epilogue: kv[m] = sum_n tanh(C[m][n] + bias[n]) * u[n] ----
    float rs[2][2] = {{0.0f, 0.0f}, {0.0f, 0.0f}};
    #pragma unroll
    for (int mt = 0; mt < 2; mt++) {
        #pragma unroll
        for (int nt = 0; nt < 4; nt++) {
            int n = n0 + nt * 8 + ((l & 3) << 1);
            float b0v = *(const float*)(smem + OFF_BIAS + n * 4);
            float b1v = *(const float*)(smem + OFF_BIAS + (n + 1) * 4);
            float u0v = *(const float*)(smem + OFF_U + n * 4);
            float u1v = *(const float*)(smem + OFF_U + (n + 1) * 4);
            rs[mt][0] += fast_tanh(acc[mt][nt][0] + b0v) * u0v
                       + fast_tanh(acc[mt][nt][1] + b1v) * u1v;
            rs[mt][1] += fast_tanh(acc[mt][nt][2] + b0v) * u0v
                       + fast_tanh(acc[mt][nt][3] + b1v) * u1v;
        }
    }
    #pragma unroll
    for (int mt = 0; mt < 2; mt++)
        #pragma unroll
        for (int h = 0; h < 2; h++) {
            float v = rs[mt][h];
            v += __shfl_xor_sync(0xFFFFFFFFu, v, 1);
            v += __shfl_xor_sync(0xFFFFFFFFu, v, 2);
            if ((l & 3) == 0) {
                int row = m0 + mt * 16 + h * 8 + (l >> 2);   // 0..63
                *(float*)(smem + OFF_PART + (row * 4 + wn) * 4) = v;
            }
        }
    __syncthreads();
    if (tid < MS) {
        float kv = *(const float*)(smem + OFF_PART + (tid * 4) * 4)
                 + *(const float*)(smem + OFF_PART + (tid * 4 + 1) * 4)
                 + *(const float*)(smem + OFF_PART + (tid * 4 + 2) * 4)
                 + *(const float*)(smem + OFF_PART + (tid * 4 + 3) * 4);
        g_kv[b * S + srow0 + tid] = kv;
        float mk = *(const float*)(smem + OFF_MASK + tid * 4);
        *(float*)(smem + OFF_W1 + tid * 4) = __expf(kv) * mk;   // |kv| <= ~10
    }
    __syncthreads();

    // ---- pooling partials from resident fp16 X (smem only) ----
    float2 p1 = make_float2(0.f, 0.f), p2 = make_float2(0.f, 0.f);
    #pragma unroll 8
    for (int s = 0; s < MS; s++) {
        uint32_t packed = *(const uint32_t*)(smem + OFF_X + s * XROWB + tid * 4);
        float2 f = __half22float2(*(const __half2*)&packed);
        float w1 = *(const float*)(smem + OFF_W1 + s * 4);
        float w2 = *(const float*)(smem + OFF_MASK + s * 4);
        p1.x += f.x * w1; p1.y += f.y * w1;
        p2.x += f.x * w2; p2.y += f.y * w2;
    }
    const size_t po = (size_t)(b * 2 + half) * D + tid * 2;
    *(float2*)(g_P1h + po) = p1;
    *(float2*)(g_P2h + po) = p2;
}

// ---------------- kernel 2: global sum of kv (double accum) ----------------
__global__ void reduce_kernel() {
    __shared__ double ssum[32];
    double acc = 0.0;
    for (int i = threadIdx.x; i < B * S; i += 1024)
        acc += (double)g_kv[i];
    #pragma unroll
    for (int o = 16; o > 0; o >>= 1)
        acc += __shfl_xor_sync(0xFFFFFFFFu, acc, o);
    if ((threadIdx.x & 31) == 0) ssum[threadIdx.x >> 5] = acc;
    __syncthreads();
    if (threadIdx.x < 32) {
        double v = ssum[threadIdx.x];
        #pragma unroll
        for (int o = 16; o > 0; o >>= 1)
            v += __shfl_xor_sync(0xFFFFFFFFu, v, o);
        if (threadIdx.x == 0) g_mv = (float)v;
    }
}

// ---------------- kernel 3: combine -> prob + pooled ----------------
__global__ __launch_bounds__(256)
void combine_kernel(const float* __restrict__ mask, float* __restrict__ out) {
    __shared__ float se[S];
    __shared__ float ssum;
    const int tid = threadIdx.x;
    const int b = blockIdx.x;
    const double mv = (double)g_mv;

    if (tid < S) {
        float kv = g_kv[b * S + tid];
        float mk = mask[b * S + tid];
        float e = (float)exp((double)kv - mv);
        se[tid] = (e + EPS) * mk;
    }
    __syncthreads();
    if (tid < 32) {
        float v = se[tid] + se[tid + 32] + se[tid + 64] + se[tid + 96];
        #pragma unroll
        for (int o = 16; o > 0; o >>= 1)
            v += __shfl_xor_sync(0xFFFFFFFFu, v, o);
        if (tid == 0) ssum = v;
    }
    __syncthreads();
    const double den = (double)ssum + (double)EPS;
    if (tid < S)
        out[B * D + b * S + tid] = (float)((double)se[tid] / den);   // prob

    const double c = exp(-mv);
    #pragma unroll
    for (int i = tid; i < D; i += 256) {
        double p1 = (double)g_P1h[(size_t)(b * 2) * D + i]
                  + (double)g_P1h[(size_t)(b * 2 + 1) * D + i];
        double p2 = (double)g_P2h[(size_t)(b * 2) * D + i]
                  + (double)g_P2h[(size_t)(b * 2 + 1) * D + i];
        out[b * D + i] = (float)((c * p1 + (double)EPS * p2) / den); // pooled
    }
}

// ---------------- launcher ----------------
extern "C" void kernel_launch(void* const* d_in, const int* in_sizes, int n_in,
                              void* d_out, int out_size) {
    const float* x    = (const float*)d_in[0];  // inputs  [B,S,D]
    const float* mask = (const float*)d_in[1];  // mask    [B,S,1]
    const float* W    = (const float*)d_in[2];  // kernel  [D,A]
    const float* bias = (const float*)d_in[3];  // bias    [A]
    const float* u    = (const float*)d_in[4];  // u_ctx   [A,1]
    float* out = (float*)d_out;                 // pooled [B,D] ++ prob [B,S]

    cudaFuncSetAttribute(gemm_kv_pool_kernel,
                         cudaFuncAttributeMaxDynamicSharedMemorySize, SMEM_TOTAL);

    prep_w_kernel<<<(D * A + 255) / 256, 256>>>(W);
    gemm_kv_pool_kernel<<<B * 2, 256, SMEM_TOTAL>>>(x, mask, bias, u);
    reduce_kernel<<<1, 1024>>>();
    combine_kernel<<<B, 256>>>(mask, out);
}

// round 15
// speedup vs baseline: 1.0501x; 1.0501x over previous
#include <cuda_runtime.h>
#include <cuda_fp16.h>
#include <cstdint>

// ---------------- problem constants ----------------
static constexpr int B = 512, S = 128, D = 512, A = 128;
static constexpr float EPS = 1e-7f;

// ---------------- device scratch (no allocs allowed) ----------------
__device__ __align__(16) __half g_wt[A * D];    // W^T fp16 [a][k]
__device__ float g_kv[B * S];
__device__ float g_mv;
__device__ __align__(16) float g_P1h[B * 2 * D];  // per-half sum_s x*exp(kv)*mask
__device__ __align__(16) float g_P2h[B * 2 * D];  // per-half sum_s x*mask

// ---------------- gemm tiling: CTA = (batch, half) -> 64 rows ----------------
static constexpr int MS     = 64;               // rows per CTA
static constexpr int KC     = 64;               // k per W chunk
static constexpr int NCHUNK = D / KC;           // 8

// X resident fp16: [64 rows][520 h] (512 data + 8 pad) = 1040 B/row
static constexpr int XROWB  = 520 * 2;          // 1040
static constexpr int XTOT_B = MS * XROWB;       // 66560
// W stage: [128 rows][72 h] = 144 B/row -> 18432 B, double-buffered
static constexpr int WROWB  = 72 * 2;
static constexpr int WBUF_B = 128 * WROWB;      // 18432
static constexpr int OFF_X    = 0;
static constexpr int OFF_W    = XTOT_B;                      // 66560
static constexpr int OFF_BIAS = OFF_W + 2 * WBUF_B;          // 103424
static constexpr int OFF_U    = OFF_BIAS + 512;
static constexpr int OFF_PART = OFF_U + 512;                 // float[64][4]
static constexpr int OFF_W1   = OFF_PART + 1024;             // exp(kv)*mask [64]
static constexpr int OFF_MASK = OFF_W1 + 256;                // mask [64]
static constexpr int SMEM_TOTAL = OFF_MASK + 256;            // 105984 (2 CTAs/SM)

// ---------------- baseline-ISA helpers (sm_100 plain) ----------------
__device__ __forceinline__ uint32_t smem_u32(const void* p) {
    return (uint32_t)__cvta_generic_to_shared(p);
}

#define CP_ASYNC16(dst, src) \
    asm volatile("cp.async.cg.shared.global [%0], [%1], 16;" :: "r"(dst), "l"(src))
#define CP_COMMIT() asm volatile("cp.async.commit_group;")
#define CP_WAIT_ALL() asm volatile("cp.async.wait_group 0;")

#define LDSM_X4(r, addr) \
    asm volatile("ldmatrix.sync.aligned.m8n8.x4.shared.b16 {%0,%1,%2,%3}, [%4];" \
        : "=r"((r)[0]), "=r"((r)[1]), "=r"((r)[2]), "=r"((r)[3]) : "r"(addr))

#define MMA_F16(d, a, b0, b1) \
    asm volatile("mma.sync.aligned.m16n8k16.row.col.f32.f16.f16.f32 " \
        "{%0,%1,%2,%3}, {%4,%5,%6,%7}, {%8,%9}, {%0,%1,%2,%3};" \
        : "+f"((d)[0]), "+f"((d)[1]), "+f"((d)[2]), "+f"((d)[3]) \
        : "r"((a)[0]), "r"((a)[1]), "r"((a)[2]), "r"((a)[3]), "r"(b0), "r"(b1))

__device__ __forceinline__ float fast_tanh(float x) {
    float a = fabsf(x);
    float t = __expf(-2.0f * a);
    float r = (1.0f - t) / (1.0f + t);
    return copysignf(r, x);
}

// ---------------- kernel 0: transpose W to fp16 ----------------
__global__ void prep_w_kernel(const float* __restrict__ W) {
    int idx = blockIdx.x * blockDim.x + threadIdx.x;
    if (idx < D * A) {
        int k = idx / A, a = idx % A;
        g_wt[a * D + k] = __float2half_rn(W[idx]);
    }
}

// ---------------- kernel 1: fused GEMM + tanh + kv + pooling ----------------
// R11 structure with X LDG prefetch distance = 2 (two register buffers):
// storeX(c) consumes loads issued two chunks earlier -> latency fully hidden.
__global__ __launch_bounds__(256, 2)
void gemm_kv_pool_kernel(const float* __restrict__ x,
                         const float* __restrict__ mask,
                         const float* __restrict__ bias,
                         const float* __restrict__ u) {
    extern __shared__ char smem[];
    const uint32_t sb = smem_u32(smem);
    const int tid = threadIdx.x;
    const int wid = tid >> 5;
    const int l   = tid & 31;
    const int b    = blockIdx.x >> 1;
    const int half = blockIdx.x & 1;
    const int srow0 = half * MS;

    if (tid < A) {
        *(float*)(smem + OFF_BIAS + tid * 4) = bias[tid];
        *(float*)(smem + OFF_U + tid * 4) = u[tid];
    }
    if (tid < MS)
        *(float*)(smem + OFF_MASK + tid * 4) = mask[b * S + srow0 + tid];

    const int wm = wid >> 2, wn = wid & 3;       // 2 x 4 warp grid
    const int m0 = wm * 32, n0 = wn * 32;

    const float* xb = x + (size_t)(b * S + srow0) * D;

    // A ldmatrix pointer (within resident X)
    const uint32_t aOff = (uint32_t)((m0 + (l & 15)) * XROWB + ((l >> 4) << 3) * 2);
    // B ldmatrix pointer (within a W stage)
    const uint32_t bOff = (uint32_t)((n0 + ((l >> 4) << 3) + (l & 7)) * WROWB
                                     + (((l >> 3) & 1) << 3) * 2);

    // X LDG geometry: 1024 float4/chunk -> 4/thread (rows xr0 + t*16)
    const int xr0 = tid >> 4, xc4 = tid & 15;
    // W cp.async: 1024 ops/chunk -> 4/thread (rows wr0 + t*32)
    const int wr0 = tid >> 3, wj = tid & 7;

    float acc[2][4][4];
    #pragma unroll
    for (int mt = 0; mt < 2; mt++)
        #pragma unroll
        for (int nt = 0; nt < 4; nt++)
            #pragma unroll
            for (int q = 0; q < 4; q++) acc[mt][nt][q] = 0.0f;

    float4 xreg[2][4];                  // two in-flight chunk buffers
    auto loadX = [&](int c, int buf) {
        #pragma unroll
        for (int t = 0; t < 4; t++) {
            int row = xr0 + t * 16;
            xreg[buf][t] = *(const float4*)(xb + (size_t)row * D + c * KC + xc4 * 4);
        }
    };
    auto storeX = [&](int c, int buf) {
        #pragma unroll
        for (int t = 0; t < 4; t++) {
            int row = xr0 + t * 16;
            __half2 h0 = __floats2half2_rn(xreg[buf][t].x, xreg[buf][t].y);
            __half2 h1 = __floats2half2_rn(xreg[buf][t].z, xreg[buf][t].w);
            *(uint2*)(smem + OFF_X + row * XROWB + (c * KC + xc4 * 4) * 2) =
                make_uint2(*(uint32_t*)&h0, *(uint32_t*)&h1);
        }
    };

    // ---- prologue: X chunks 0,1 in flight; W chunk 0 cp.async ----
    loadX(0, 0);
    loadX(1, 1);
    {
        const uint32_t wB = sb + OFF_W;
        #pragma unroll
        for (int t = 0; t < 4; t++) {
            int row = wr0 + t * 32;
            CP_ASYNC16(wB + row * WROWB + wj * 16,
                       (const char*)(g_wt + (size_t)row * D) + wj * 16);
        }
        CP_COMMIT();
    }

    #pragma unroll 1
    for (int c = 0; c < NCHUNK; c++) {
        storeX(c, c & 1);                   // consumes LDGs issued 2 chunks ago
        if (c + 2 < NCHUNK) loadX(c + 2, c & 1);   // refill freed buffer
        CP_WAIT_ALL();                      // W chunk c resident
        __syncthreads();                    // X_c + W_c visible

        if (c + 1 < NCHUNK) {
            const uint32_t wB = sb + OFF_W + ((c + 1) & 1) * WBUF_B;
            #pragma unroll
            for (int t = 0; t < 4; t++) {
                int row = wr0 + t * 32;
                CP_ASYNC16(wB + row * WROWB + wj * 16,
                           (const char*)(g_wt + (size_t)row * D + (c + 1) * KC) + wj * 16);
            }
            CP_COMMIT();
        }

        const uint32_t wH = sb + OFF_W + (c & 1) * WBUF_B;
        #pragma unroll
        for (int ks = 0; ks < 4; ks++) {
            const int g = c * 4 + ks;
            uint32_t ah[2][4], bb[2][4];
            LDSM_X4(ah[0], sb + OFF_X + aOff + g * 32);
            LDSM_X4(ah[1], sb + OFF_X + aOff + 16 * XROWB + g * 32);
            LDSM_X4(bb[0], wH + bOff + ks * 32);
            LDSM_X4(bb[1], wH + bOff + 16 * WROWB + ks * 32);
            #pragma unroll
            for (int mt = 0; mt < 2; mt++)
                #pragma unroll
                for (int nb = 0; nb < 2; nb++) {
                    MMA_F16(acc[mt][2 * nb],     ah[mt], bb[nb][0], bb[nb][1]);
                    MMA_F16(acc[mt][2 * nb + 1], ah[mt], bb[nb][2], bb[nb][3]);
                }
        }
        __syncthreads();                    // MMA done before next STS/W-overwrite
    }

    // ---- kv epilogue: kv[m] = sum_n tanh(C[m][n] + bias[n]) * u[n] ----
    float rs[2][2] = {{0.0f, 0.0f}, {0.0f, 0.0f}};
    #pragma unroll
    for (int mt = 0; mt < 2; mt++) {
        #pragma unroll
        for (int nt = 0; nt < 4; nt++) {
            int n = n0 + nt * 8 + ((l & 3) << 1);
            float b0v = *(const float*)(smem + OFF_BIAS + n * 4);
            float b1v = *(const float*)(smem + OFF_BIAS + (n + 1) * 4);
            float u0v = *(const float*)(smem + OFF_U + n * 4);
            float u1v = *(const float*)(smem + OFF_U + (n + 1) * 4);
            rs[mt][0] += fast_tanh(acc[mt][nt][0] + b0v) * u0v
                       + fast_tanh(acc[mt][nt][1] + b1v) * u1v;
            rs[mt][1] += fast_tanh(acc[mt][nt][2] + b0v) * u0v
                       + fast_tanh(acc[mt][nt][3] + b1v) * u1v;
        }
    }
    #pragma unroll
    for (int mt = 0; mt < 2; mt++)
        #pragma unroll
        for (int h = 0; h < 2; h++) {
            float v = rs[mt][h];
            v += __shfl_xor_sync(0xFFFFFFFFu, v, 1);
            v += __shfl_xor_sync(0xFFFFFFFFu, v, 2);
            if ((l & 3) == 0) {
                int row = m0 + mt * 16 + h * 8 + (l >> 2);   // 0..63
                *(float*)(smem + OFF_PART + (row * 4 + wn) * 4) = v;
            }
        }
    __syncthreads();
    if (tid < MS) {
        float kv = *(const float*)(smem + OFF_PART + (tid * 4) * 4)
                 + *(const float*)(smem + OFF_PART + (tid * 4 + 1) * 4)
                 + *(const float*)(smem + OFF_PART + (tid * 4 + 2) * 4)
                 + *(const float*)(smem + OFF_PART + (tid * 4 + 3) * 4);
        g_kv[b * S + srow0 + tid] = kv;
        float mk = *(const float*)(smem + OFF_MASK + tid * 4);
        *(float*)(smem + OFF_W1 + tid * 4) = __expf(kv) * mk;   // |kv| <= ~10
    }
    __syncthreads();

    // ---- pooling partials from resident fp16 X (smem only) ----
    float2 p1 = make_float2(0.f, 0.f), p2 = make_float2(0.f, 0.f);
    #pragma unroll 8
    for (int s = 0; s < MS; s++) {
        uint32_t packed = *(const uint32_t*)(smem + OFF_X + s * XROWB + tid * 4);
        float2 f = __half22float2(*(const __half2*)&packed);
        float w1 = *(const float*)(smem + OFF_W1 + s * 4);
        float w2 = *(const float*)(smem + OFF_MASK + s * 4);
        p1.x += f.x * w1; p1.y += f.y * w1;
        p2.x += f.x * w2; p2.y += f.y * w2;
    }
    const size_t po = (size_t)(b * 2 + half) * D + tid * 2;
    *(float2*)(g_P1h + po) = p1;
    *(float2*)(g_P2h + po) = p2;
}

// ---------------- kernel 2: global sum of kv (double accum) ----------------
__global__ void reduce_kernel() {
    __shared__ double ssum[32];
    double acc = 0.0;
    for (int i = threadIdx.x; i < B * S; i += 1024)
        acc += (double)g_kv[i];
    #pragma unroll
    for (int o = 16; o > 0; o >>= 1)
        acc += __shfl_xor_sync(0xFFFFFFFFu, acc, o);
    if ((threadIdx.x & 31) == 0) ssum[threadIdx.x >> 5] = acc;
    __syncthreads();
    if (threadIdx.x < 32) {
        double v = ssum[threadIdx.x];
        #pragma unroll
        for (int o = 16; o > 0; o >>= 1)
            v += __shfl_xor_sync(0xFFFFFFFFu, v, o);
        if (threadIdx.x == 0) g_mv = (float)v;
    }
}

// ---------------- kernel 3: combine -> prob + pooled ----------------
__global__ __launch_bounds__(256)
void combine_kernel(const float* __restrict__ mask, float* __restrict__ out) {
    __shared__ float se[S];
    __shared__ float ssum;
    const int tid = threadIdx.x;
    const int b = blockIdx.x;
    const double mv = (double)g_mv;

    if (tid < S) {
        float kv = g_kv[b * S + tid];
        float mk = mask[b * S + tid];
        float e = (float)exp((double)kv - mv);
        se[tid] = (e + EPS) * mk;
    }
    __syncthreads();
    if (tid < 32) {
        float v = se[tid] + se[tid + 32] + se[tid + 64] + se[tid + 96];
        #pragma unroll
        for (int o = 16; o > 0; o >>= 1)
            v += __shfl_xor_sync(0xFFFFFFFFu, v, o);
        if (tid == 0) ssum = v;
    }
    __syncthreads();
    const double den = (double)ssum + (double)EPS;
    if (tid < S)
        out[B * D + b * S + tid] = (float)((double)se[tid] / den);   // prob

    const double c = exp(-mv);
    #pragma unroll
    for (int i = tid; i < D; i += 256) {
        double p1 = (double)g_P1h[(size_t)(b * 2) * D + i]
                  + (double)g_P1h[(size_t)(b * 2 + 1) * D + i];
        double p2 = (double)g_P2h[(size_t)(b * 2) * D + i]
                  + (double)g_P2h[(size_t)(b * 2 + 1) * D + i];
        out[b * D + i] = (float)((c * p1 + (double)EPS * p2) / den); // pooled
    }
}

// ---------------- launcher ----------------
extern "C" void kernel_launch(void* const* d_in, const int* in_sizes, int n_in,
                              void* d_out, int out_size) {
    const float* x    = (const float*)d_in[0];  // inputs  [B,S,D]
    const float* mask = (const float*)d_in[1];  // mask    [B,S,1]
    const float* W    = (const float*)d_in[2];  // kernel  [D,A]
    const float* bias = (const float*)d_in[3];  // bias    [A]
    const float* u    = (const float*)d_in[4];  // u_ctx   [A,1]
    float* out = (float*)d_out;                 // pooled [B,D] ++ prob [B,S]

    cudaFuncSetAttribute(gemm_kv_pool_kernel,
                         cudaFuncAttributeMaxDynamicSharedMemorySize, SMEM_TOTAL);

    prep_w_kernel<<<(D * A + 255) / 256, 256>>>(W);
    gemm_kv_pool_kernel<<<B * 2, 256, SMEM_TOTAL>>>(x, mask, bias, u);
    reduce_kernel<<<1, 1024>>>();
    combine_kernel<<<B, 256>>>(mask, out);
}

// round 16
// speedup vs baseline: 1.3562x; 1.2914x over previous
#include <cuda_runtime.h>
#include <cuda_fp16.h>
#include <cstdint>

// ---------------- problem constants ----------------
static constexpr int B = 512, S = 128, D = 512, A = 128;
static constexpr float EPS = 1e-7f;

// ---------------- device scratch (no allocs allowed) ----------------
__device__ __align__(16) __half g_wt[A * D];    // W^T fp16 [a][k]
__device__ float g_kv[B * S];
__device__ float g_mv;
__device__ __align__(16) float g_P1h[B * 2 * D];  // per-half sum_s x*exp(kv)*mask
__device__ __align__(16) float g_P2h[B * 2 * D];  // per-half sum_s x*mask

// ---------------- gemm tiling: CTA = (batch, half) -> 64 rows ----------------
static constexpr int MS     = 64;               // rows per CTA
static constexpr int KC     = 64;               // k per W chunk
static constexpr int NCHUNK = D / KC;           // 8

// X resident fp16: [64 rows][520 h] (512 data + 8 pad) = 1040 B/row
static constexpr int XROWB  = 520 * 2;          // 1040
static constexpr int XTOT_B = MS * XROWB;       // 66560
// W stage: [128 rows][72 h] = 144 B/row -> 18432 B, double-buffered
static constexpr int WROWB  = 72 * 2;
static constexpr int WBUF_B = 128 * WROWB;      // 18432
static constexpr int OFF_X    = 0;
static constexpr int OFF_W    = XTOT_B;                      // 66560
static constexpr int OFF_BIAS = OFF_W + 2 * WBUF_B;          // 103424
static constexpr int OFF_U    = OFF_BIAS + 512;
static constexpr int OFF_PART = OFF_U + 512;                 // float[64][4]
static constexpr int OFF_W1   = OFF_PART + 1024;             // exp(kv)*mask [64]
static constexpr int OFF_MASK = OFF_W1 + 256;                // mask [64]
static constexpr int SMEM_TOTAL = OFF_MASK + 256;            // 105984 (2 CTAs/SM)

// ---------------- baseline-ISA helpers (sm_100 plain) ----------------
__device__ __forceinline__ uint32_t smem_u32(const void* p) {
    return (uint32_t)__cvta_generic_to_shared(p);
}

#define CP_ASYNC16(dst, src) \
    asm volatile("cp.async.cg.shared.global [%0], [%1], 16;" :: "r"(dst), "l"(src))
#define CP_COMMIT() asm volatile("cp.async.commit_group;")
#define CP_WAIT_ALL() asm volatile("cp.async.wait_group 0;")

#define LDSM_X4(r, addr) \
    asm volatile("ldmatrix.sync.aligned.m8n8.x4.shared.b16 {%0,%1,%2,%3}, [%4];" \
        : "=r"((r)[0]), "=r"((r)[1]), "=r"((r)[2]), "=r"((r)[3]) : "r"(addr))

#define MMA_F16(d, a, b0, b1) \
    asm volatile("mma.sync.aligned.m16n8k16.row.col.f32.f16.f16.f32 " \
        "{%0,%1,%2,%3}, {%4,%5,%6,%7}, {%8,%9}, {%0,%1,%2,%3};" \
        : "+f"((d)[0]), "+f"((d)[1]), "+f"((d)[2]), "+f"((d)[3]) \
        : "r"((a)[0]), "r"((a)[1]), "r"((a)[2]), "r"((a)[3]), "r"(b0), "r"(b1))

__device__ __forceinline__ float fast_tanh(float x) {
    float a = fabsf(x);
    float t = __expf(-2.0f * a);
    float r = (1.0f - t) / (1.0f + t);
    return copysignf(r, x);
}

// ---------------- kernel 0: transpose W to fp16 ----------------
__global__ void prep_w_kernel(const float* __restrict__ W) {
    int idx = blockIdx.x * blockDim.x + threadIdx.x;
    if (idx < D * A) {
        int k = idx / A, a = idx % A;
        g_wt[a * D + k] = __float2half_rn(W[idx]);
    }
}

// ---------------- kernel 1: fused GEMM + tanh + kv + pooling ----------------
// EXACT R11 structure (measured 69.7us total): CTA = (batch, half), 64 s-rows,
// X fp16 resident in smem, W double-buffered cp.async, pool tail from smem.
__global__ __launch_bounds__(256, 2)
void gemm_kv_pool_kernel(const float* __restrict__ x,
                         const float* __restrict__ mask,
                         const float* __restrict__ bias,
                         const float* __restrict__ u) {
    extern __shared__ char smem[];
    const uint32_t sb = smem_u32(smem);
    const int tid = threadIdx.x;
    const int wid = tid >> 5;
    const int l   = tid & 31;
    const int b    = blockIdx.x >> 1;
    const int half = blockIdx.x & 1;
    const int srow0 = half * MS;

    if (tid < A) {
        *(float*)(smem + OFF_BIAS + tid * 4) = bias[tid];
        *(float*)(smem + OFF_U + tid * 4) = u[tid];
    }
    if (tid < MS)
        *(float*)(smem + OFF_MASK + tid * 4) = mask[b * S + srow0 + tid];

    const int wm = wid >> 2, wn = wid & 3;       // 2 x 4 warp grid
    const int m0 = wm * 32, n0 = wn * 32;

    const float* xb = x + (size_t)(b * S + srow0) * D;

    // A ldmatrix pointer (within resident X)
    const uint32_t aOff = (uint32_t)((m0 + (l & 15)) * XROWB + ((l >> 4) << 3) * 2);
    // B ldmatrix pointer (within a W stage)
    const uint32_t bOff = (uint32_t)((n0 + ((l >> 4) << 3) + (l & 7)) * WROWB
                                     + (((l >> 3) & 1) << 3) * 2);

    // X LDG geometry: 1024 float4/chunk -> 4/thread (rows xr0 + t*16)
    const int xr0 = tid >> 4, xc4 = tid & 15;
    // W cp.async: 1024 ops/chunk -> 4/thread (rows wr0 + t*32)
    const int wr0 = tid >> 3, wj = tid & 7;

    float acc[2][4][4];
    #pragma unroll
    for (int mt = 0; mt < 2; mt++)
        #pragma unroll
        for (int nt = 0; nt < 4; nt++)
            #pragma unroll
            for (int q = 0; q < 4; q++) acc[mt][nt][q] = 0.0f;

    float4 xreg[4];
    auto loadX = [&](int c) {
        #pragma unroll
        for (int t = 0; t < 4; t++) {
            int row = xr0 + t * 16;
            xreg[t] = *(const float4*)(xb + (size_t)row * D + c * KC + xc4 * 4);
        }
    };
    auto storeX = [&](int c) {
        #pragma unroll
        for (int t = 0; t < 4; t++) {
            int row = xr0 + t * 16;
            __half2 h0 = __floats2half2_rn(xreg[t].x, xreg[t].y);
            __half2 h1 = __floats2half2_rn(xreg[t].z, xreg[t].w);
            *(uint2*)(smem + OFF_X + row * XROWB + (c * KC + xc4 * 4) * 2) =
                make_uint2(*(uint32_t*)&h0, *(uint32_t*)&h1);
        }
    };

    // ---- prologue: X chunk 0 LDGs; W chunk 0 cp.async ----
    loadX(0);
    {
        const uint32_t wB = sb + OFF_W;
        #pragma unroll
        for (int t = 0; t < 4; t++) {
            int row = wr0 + t * 32;
            CP_ASYNC16(wB + row * WROWB + wj * 16,
                       (const char*)(g_wt + (size_t)row * D) + wj * 16);
        }
        CP_COMMIT();
    }

    #pragma unroll 1
    for (int c = 0; c < NCHUNK; c++) {
        storeX(c);                          // cvt+STS chunk c (resident)
        if (c + 1 < NCHUNK) loadX(c + 1);   // LDGs drain during MMA
        CP_WAIT_ALL();                      // W chunk c resident
        __syncthreads();                    // X_c + W_c visible

        if (c + 1 < NCHUNK) {
            const uint32_t wB = sb + OFF_W + ((c + 1) & 1) * WBUF_B;
            #pragma unroll
            for (int t = 0; t < 4; t++) {
                int row = wr0 + t * 32;
                CP_ASYNC16(wB + row * WROWB + wj * 16,
                           (const char*)(g_wt + (size_t)row * D + (c + 1) * KC) + wj * 16);
            }
            CP_COMMIT();
        }

        const uint32_t wH = sb + OFF_W + (c & 1) * WBUF_B;
        #pragma unroll
        for (int ks = 0; ks < 4; ks++) {
            const int g = c * 4 + ks;
            uint32_t ah[2][4], bb[2][4];
            LDSM_X4(ah[0], sb + OFF_X + aOff + g * 32);
            LDSM_X4(ah[1], sb + OFF_X + aOff + 16 * XROWB + g * 32);
            LDSM_X4(bb[0], wH + bOff + ks * 32);
            LDSM_X4(bb[1], wH + bOff + 16 * WROWB + ks * 32);
            #pragma unroll
            for (int mt = 0; mt < 2; mt++)
                #pragma unroll
                for (int nb = 0; nb < 2; nb++) {
                    MMA_F16(acc[mt][2 * nb],     ah[mt], bb[nb][0], bb[nb][1]);
                    MMA_F16(acc[mt][2 * nb + 1], ah[mt], bb[nb][2], bb[nb][3]);
                }
        }
        __syncthreads();                    // MMA done before next STS/W-overwrite
    }

    // ---- kv epilogue: kv[m] = sum_n tanh(C[m][n] + bias[n]) * u[n] ----
    float rs[2][2] = {{0.0f, 0.0f}, {0.0f, 0.0f}};
    #pragma unroll
    for (int mt = 0; mt < 2; mt++) {
        #pragma unroll
        for (int nt = 0; nt < 4; nt++) {
            int n = n0 + nt * 8 + ((l & 3) << 1);
            float b0v = *(const float*)(smem + OFF_BIAS + n * 4);
            float b1v = *(const float*)(smem + OFF_BIAS + (n + 1) * 4);
            float u0v = *(const float*)(smem + OFF_U + n * 4);
            float u1v = *(const float*)(smem + OFF_U + (n + 1) * 4);
            rs[mt][0] += fast_tanh(acc[mt][nt][0] + b0v) * u0v
                       + fast_tanh(acc[mt][nt][1] + b1v) * u1v;
            rs[mt][1] += fast_tanh(acc[mt][nt][2] + b0v) * u0v
                       + fast_tanh(acc[mt][nt][3] + b1v) * u1v;
        }
    }
    #pragma unroll
    for (int mt = 0; mt < 2; mt++)
        #pragma unroll
        for (int h = 0; h < 2; h++) {
            float v = rs[mt][h];
            v += __shfl_xor_sync(0xFFFFFFFFu, v, 1);
            v += __shfl_xor_sync(0xFFFFFFFFu, v, 2);
            if ((l & 3) == 0) {
                int row = m0 + mt * 16 + h * 8 + (l >> 2);   // 0..63
                *(float*)(smem + OFF_PART + (row * 4 + wn) * 4) = v;
            }
        }
    __syncthreads();
    if (tid < MS) {
        float kv = *(const float*)(smem + OFF_PART + (tid * 4) * 4)
                 + *(const float*)(smem + OFF_PART + (tid * 4 + 1) * 4)
                 + *(const float*)(smem + OFF_PART + (tid * 4 + 2) * 4)
                 + *(const float*)(smem + OFF_PART + (tid * 4 + 3) * 4);
        g_kv[b * S + srow0 + tid] = kv;
        float mk = *(const float*)(smem + OFF_MASK + tid * 4);
        *(float*)(smem + OFF_W1 + tid * 4) = __expf(kv) * mk;   // |kv| <= ~10
    }
    __syncthreads();

    // ---- pooling partials from resident fp16 X (smem only) ----
    float2 p1 = make_float2(0.f, 0.f), p2 = make_float2(0.f, 0.f);
    #pragma unroll 8
    for (int s = 0; s < MS; s++) {
        uint32_t packed = *(const uint32_t*)(smem + OFF_X + s * XROWB + tid * 4);
        float2 f = __half22float2(*(const __half2*)&packed);
        float w1 = *(const float*)(smem + OFF_W1 + s * 4);
        float w2 = *(const float*)(smem + OFF_MASK + s * 4);
        p1.x += f.x * w1; p1.y += f.y * w1;
        p2.x += f.x * w2; p2.y += f.y * w2;
    }
    const size_t po = (size_t)(b * 2 + half) * D + tid * 2;
    *(float2*)(g_P1h + po) = p1;
    *(float2*)(g_P2h + po) = p2;
}

// ---------------- kernel 2: global sum of kv (double accum) ----------------
__global__ void reduce_kernel() {
    __shared__ double ssum[32];
    double acc = 0.0;
    for (int i = threadIdx.x; i < B * S; i += 1024)
        acc += (double)g_kv[i];
    #pragma unroll
    for (int o = 16; o > 0; o >>= 1)
        acc += __shfl_xor_sync(0xFFFFFFFFu, acc, o);
    if ((threadIdx.x & 31) == 0) ssum[threadIdx.x >> 5] = acc;
    __syncthreads();
    if (threadIdx.x < 32) {
        double v = ssum[threadIdx.x];
        #pragma unroll
        for (int o = 16; o > 0; o >>= 1)
            v += __shfl_xor_sync(0xFFFFFFFFu, v, o);
        if (threadIdx.x == 0) g_mv = (float)v;
    }
}

// ---------------- kernel 3: combine -> prob + pooled (fp32 fast path) -------
// One double exp/div pair per CTA (thread 0); all bulk math fp32 + float4.
__global__ __launch_bounds__(128)
void combine_kernel(const float* __restrict__ mask, float* __restrict__ out) {
    __shared__ float se[S];
    __shared__ float s_c, s_invden;
    const int tid = threadIdx.x;
    const int b = blockIdx.x;
    const float mv = g_mv;

    float kv = g_kv[b * S + tid];
    float mk = mask[b * S + tid];
    float e = expf(kv - mv);                 // validated fp32 path (R5-R8)
    float kve = (e + EPS) * mk;
    se[tid] = kve;
    __syncthreads();
    if (tid < 32) {
        float v = se[tid] + se[tid + 32] + se[tid + 64] + se[tid + 96];
        #pragma unroll
        for (int o = 16; o > 0; o >>= 1)
            v += __shfl_xor_sync(0xFFFFFFFFu, v, o);
        if (tid == 0) {
            double den = (double)v + (double)EPS;
            s_invden = (float)(1.0 / den);
            s_c = (float)exp(-(double)mv);   // underflow-safe: if 0, eps term rules
        }
    }
    __syncthreads();
    const float invden = s_invden;
    const float c = s_c;

    out[B * D + b * S + tid] = kve * invden;            // prob

    // pooled: 128 threads x float4 covers D=512
    const size_t base0 = (size_t)(b * 2) * D + tid * 4;
    const size_t base1 = (size_t)(b * 2 + 1) * D + tid * 4;
    float4 a1 = *(const float4*)(g_P1h + base0);
    float4 b1v = *(const float4*)(g_P1h + base1);
    float4 a2 = *(const float4*)(g_P2h + base0);
    float4 b2v = *(const float4*)(g_P2h + base1);
    float4 r;
    r.x = (c * (a1.x + b1v.x) + EPS * (a2.x + b2v.x)) * invden;
    r.y = (c * (a1.y + b1v.y) + EPS * (a2.y + b2v.y)) * invden;
    r.z = (c * (a1.z + b1v.z) + EPS * (a2.z + b2v.z)) * invden;
    r.w = (c * (a1.w + b1v.w) + EPS * (a2.w + b2v.w)) * invden;
    *(float4*)(out + b * D + tid * 4) = r;              // pooled
}

// ---------------- launcher ----------------
extern "C" void kernel_launch(void* const* d_in, const int* in_sizes, int n_in,
                              void* d_out, int out_size) {
    const float* x    = (const float*)d_in[0];  // inputs  [B,S,D]
    const float* mask = (const float*)d_in[1];  // mask    [B,S,1]
    const float* W    = (const float*)d_in[2];  // kernel  [D,A]
    const float* bias = (const float*)d_in[3];  // bias    [A]
    const float* u    = (const float*)d_in[4];  // u_ctx   [A,1]
    float* out = (float*)d_out;                 // pooled [B,D] ++ prob [B,S]

    cudaFuncSetAttribute(gemm_kv_pool_kernel,
                         cudaFuncAttributeMaxDynamicSharedMemorySize, SMEM_TOTAL);

    prep_w_kernel<<<(D * A + 255) / 256, 256>>>(W);
    gemm_kv_pool_kernel<<<B * 2, 256, SMEM_TOTAL>>>(x, mask, bias, u);
    reduce_kernel<<<1, 1024>>>();
    combine_kernel<<<B, 128>>>(mask, out);
}